// round 14
// baseline (speedup 1.0000x reference)
#include <cuda_runtime.h>
#include <math.h>

#define C_DIM 256
#define ROWS  16          // rows (points) per warp (even; pairing step = 2)
#define MAX_B 1024

__device__ int   d_off[MAX_B + 1];
__device__ float d_mean[MAX_B * 3];
// Quadratic-form coefficients for analytic LN1 stats.
__device__ float d_qc[14];

__device__ __forceinline__ void warp_red4(float& a, float& b, float& c, float& d) {
#pragma unroll
    for (int o = 16; o; o >>= 1) {
        a += __shfl_xor_sync(0xffffffffu, a, o);
        b += __shfl_xor_sync(0xffffffffu, b, o);
        c += __shfl_xor_sync(0xffffffffu, c, o);
        d += __shfl_xor_sync(0xffffffffu, d, o);
    }
}

// ---------------------------------------------------------------------------
// Prep kernel: blocks 0..B-1 per-scene coord means + offsets; block B the 14
// quadratic-form coefficients.
// ---------------------------------------------------------------------------
__global__ void prep_kernel(const float* __restrict__ coord,
                            const void* __restrict__ lengths_raw,
                            const float* __restrict__ w_xyz,
                            const float* __restrict__ b_xyz,
                            int N, int B) {
    if ((int)blockIdx.x == B) {
        if (threadIdx.x < 256) {
            int c = threadIdx.x;
            float w0 = w_xyz[c];
            float w1 = w_xyz[C_DIM + c];
            float w2 = w_xyz[2 * C_DIM + c];
            float bb = b_xyz[c];
            float loc[14] = { w0, w1, w2, bb,
                              w0 * w0, w1 * w1, w2 * w2,
                              w0 * w1, w0 * w2, w1 * w2,
                              w0 * bb, w1 * bb, w2 * bb,
                              bb * bb };
#pragma unroll
            for (int k = 0; k < 14; k++)
#pragma unroll
                for (int o = 16; o; o >>= 1)
                    loc[k] += __shfl_xor_sync(0xffffffffu, loc[k], o);
            __shared__ float sh[8][14];
            int w = threadIdx.x >> 5, l = threadIdx.x & 31;
            if (l == 0)
#pragma unroll
                for (int k = 0; k < 14; k++) sh[w][k] = loc[k];
            __syncthreads();
            if (threadIdx.x == 0) {
#pragma unroll
                for (int k = 0; k < 14; k++) {
                    double s = 0.0;
                    for (int ww = 0; ww < 8; ww++) s += (double)sh[ww][k];
                    d_qc[k] = (float)s;
                }
            }
        }
        return;
    }

    int b = blockIdx.x;
    __shared__ long long sh_start, sh_len;
    if (threadIdx.x == 0) {
        const int* i32 = (const int*)lengths_raw;
        long long sum32 = 0;
        for (int k = 0; k < B; k++) sum32 += (long long)i32[k];
        bool is64 = (sum32 != (long long)N);
        const long long* i64 = (const long long*)lengths_raw;
        long long start = 0;
        for (int k = 0; k < b; k++)
            start += is64 ? i64[k] : (long long)i32[k];
        long long len = is64 ? i64[b] : (long long)i32[b];
        sh_start = start;
        sh_len   = len;
        d_off[b] = (int)start;
        if (b == B - 1) d_off[B] = (int)(start + len);
    }
    __syncthreads();
    long long start = sh_start, len = sh_len;

    float sx = 0.f, sy = 0.f, sz = 0.f;
    for (long long t = threadIdx.x; t < len; t += blockDim.x) {
        const float* p = coord + (start + t) * 3;
        sx += p[0]; sy += p[1]; sz += p[2];
    }
#pragma unroll
    for (int o = 16; o; o >>= 1) {
        sx += __shfl_xor_sync(0xffffffffu, sx, o);
        sy += __shfl_xor_sync(0xffffffffu, sy, o);
        sz += __shfl_xor_sync(0xffffffffu, sz, o);
    }
    __shared__ float red[32][3];
    int w = threadIdx.x >> 5, l = threadIdx.x & 31;
    if (l == 0) { red[w][0] = sx; red[w][1] = sy; red[w][2] = sz; }
    __syncthreads();
    if (threadIdx.x == 0) {
        float ax = 0.f, ay = 0.f, az = 0.f;
        int nw = (blockDim.x + 31) >> 5;
        for (int k = 0; k < nw; k++) { ax += red[k][0]; ay += red[k][1]; az += red[k][2]; }
        long long d = len > 0 ? len : 1;
        float inv = 1.0f / (float)d;
        d_mean[b * 3 + 0] = ax * inv;
        d_mean[b * 3 + 1] = ay * inv;
        d_mean[b * 3 + 2] = az * inv;
    }
}

// ---------------------------------------------------------------------------
// Fused kernel. One warp per 16 rows, 8 channels per lane, rows paired.
// ALL params in transposed conflict-free smem (zero conv regs), freeing the
// register file for 3 resident blocks (24 warps/SM):
//   s_wb[j*32+lane]  = float4{w0,w1,w2,bx}   (LDS.128)
//   s_cv[j*32+lane]  = float4{wc0,wc1,wc2,bc} (LDS.128)
//   s_ab1[j*32+lane] = float2{g1,be1}         (LDS.64)
//   s_ab2[j*32+lane] = float2{g2,be2}         (LDS.64)
// ---------------------------------------------------------------------------
__global__ void __launch_bounds__(256, 3)
fused_xcpe_kernel(const float* __restrict__ feat,
                  const float* __restrict__ coord,
                  const float* __restrict__ w_xyz,  const float* __restrict__ b_xyz,
                  const float* __restrict__ g1,     const float* __restrict__ be1,
                  const float* __restrict__ w_conv, const float* __restrict__ b_conv,
                  const float* __restrict__ g2,     const float* __restrict__ be2,
                  float* __restrict__ out, int N) {
    __shared__ float4 s_wb[C_DIM];            // 4 KB
    __shared__ float4 s_cv[C_DIM];            // 4 KB
    __shared__ float2 s_ab1[C_DIM];           // 2 KB
    __shared__ float2 s_ab2[C_DIM];           // 2 KB
    __shared__ float  sqc[14];
    for (int idx = threadIdx.x; idx < C_DIM; idx += blockDim.x) {
        int l = idx & 31, j = idx >> 5;
        int c = l * 8 + j;
        s_wb[idx]  = make_float4(w_xyz[c], w_xyz[C_DIM + c], w_xyz[2 * C_DIM + c], b_xyz[c]);
        s_cv[idx]  = make_float4(w_conv[c * 3 + 0], w_conv[c * 3 + 1],
                                 w_conv[c * 3 + 2], b_conv[c]);
        s_ab1[idx] = make_float2(g1[c], be1[c]);
        s_ab2[idx] = make_float2(g2[c], be2[c]);
    }
    if (threadIdx.x < 14) sqc[threadIdx.x] = d_qc[threadIdx.x];
    __syncthreads();

    const int lane = threadIdx.x & 31;
    const int warp = blockIdx.x * (blockDim.x >> 5) + (threadIdx.x >> 5);
    int r0 = warp * ROWS;
    if (r0 >= N) return;
    int r1 = min(r0 + ROWS, N);
    const int c0 = lane * 8;

    int s = 0;
    while (r0 >= d_off[s + 1]) s++;
    int sb = d_off[s], se = d_off[s + 1];

    float fA[8], fB[8], fC[8], fD[8];

    // f(i) = feat(i) + gelu(LN1(xyz_c @ W + b)), analytic LN1 stats.
    auto compute_f = [&](int i, int sc, float* f) {
        const float* frow = feat + (size_t)i * C_DIM + c0;
        float4 e0 = *(const float4*)frow;
        float4 e1 = *(const float4*)(frow + 4);
        float x = coord[3 * i + 0] - d_mean[sc * 3 + 0];
        float y = coord[3 * i + 1] - d_mean[sc * 3 + 1];
        float z = coord[3 * i + 2] - d_mean[sc * 3 + 2];
        float mu = fmaf(x, sqc[0], fmaf(y, sqc[1], fmaf(z, sqc[2], sqc[3]))) * (1.0f / C_DIM);
        float q  = fmaf(x * x, sqc[4],
                   fmaf(y * y, sqc[5],
                   fmaf(z * z, sqc[6], sqc[13])));
        float qx = fmaf(x * y, sqc[7],
                   fmaf(x * z, sqc[8],
                   fmaf(y * z, sqc[9],
                   fmaf(x, sqc[10], fmaf(y, sqc[11], z * sqc[12])))));
        float var = fmaf(2.0f, qx, q) * (1.0f / C_DIM) - mu * mu;
        float rs  = rsqrtf(var + 1e-5f);
        float fe[8] = { e0.x, e0.y, e0.z, e0.w, e1.x, e1.y, e1.z, e1.w };
#pragma unroll
        for (int j = 0; j < 8; j++) {
            float4 wb = s_wb[j * 32 + lane];
            float2 ab = s_ab1[j * 32 + lane];
            float v = fmaf(x, wb.x, fmaf(y, wb.y, fmaf(z, wb.z, wb.w)));
            float t  = fmaf((v - mu) * rs, ab.x, ab.y);
            float gl = 0.5f * t * (1.0f + erff(t * 0.7071067811865475f));
            f[j] = fe[j] + gl;
        }
    };

    // Conv + residual for one row; accumulates LN2 partial sums.
    auto conv_h = [&](int i, const float* fp, const float* fc, const float* fn,
                      bool hasP, bool hasN, float* h, float& sm, float& sq) {
        const float* frow = feat + (size_t)i * C_DIM + c0;
        float4 e0 = *(const float4*)frow;
        float4 e1 = *(const float4*)(frow + 4);
        float fe[8] = { e0.x, e0.y, e0.z, e0.w, e1.x, e1.y, e1.z, e1.w };
        sm = 0.f; sq = 0.f;
        if (hasP & hasN) {
#pragma unroll
            for (int j = 0; j < 8; j++) {
                float4 cv4 = s_cv[j * 32 + lane];
                float cv = fmaf(cv4.x, fp[j],
                           fmaf(cv4.y, fc[j],
                           fmaf(cv4.z, fn[j], cv4.w)));
                float hh = fe[j] + cv;
                h[j] = hh; sm += hh; sq = fmaf(hh, hh, sq);
            }
        } else {
            float mp = hasP ? 1.f : 0.f, mn = hasN ? 1.f : 0.f;
#pragma unroll
            for (int j = 0; j < 8; j++) {
                float4 cv4 = s_cv[j * 32 + lane];
                float cv = fmaf(cv4.x, mp * fp[j],
                           fmaf(cv4.y, fc[j],
                           fmaf(cv4.z, mn * fn[j], cv4.w)));
                float hh = fe[j] + cv;
                h[j] = hh; sm += hh; sq = fmaf(hh, hh, sq);
            }
        }
    };

    // LN2 affine + store for one row given reduced stats.
    auto store_ln = [&](int i, const float* h, float sm, float sq) {
        float mu  = sm * (1.0f / C_DIM);
        float var = sq * (1.0f / C_DIM) - mu * mu;
        float rs  = rsqrtf(var + 1e-5f);
        float o[8];
#pragma unroll
        for (int j = 0; j < 8; j++) {
            float2 ab = s_ab2[j * 32 + lane];
            o[j] = fmaf((h[j] - mu) * rs, ab.x, ab.y);
        }
        float* orow = out + (size_t)i * C_DIM + c0;
        *(float4*)orow       = make_float4(o[0], o[1], o[2], o[3]);
        *(float4*)(orow + 4) = make_float4(o[4], o[5], o[6], o[7]);
    };

    // Prologue.
    if (r0 > 0) compute_f(r0 - 1, s, fA);
    else {
#pragma unroll
        for (int j = 0; j < 8; j++) fA[j] = 0.f;
    }
    compute_f(r0, s, fB);

    for (int i = r0; i < r1; i += 2) {
        int i1 = i + 1, i2 = i + 2;
        int s1 = s, sb1 = sb, se1 = se;
        if (i1 < N) { while (i1 >= se1) { s1++; sb1 = se1; se1 = d_off[s1 + 1]; } }
        int s2 = s1, sb2 = sb1, se2 = se1;
        if (i2 < N) { while (i2 >= se2) { s2++; sb2 = se2; se2 = d_off[s2 + 1]; } }

        // Two independent compute_f chains (ILP on erff + LDG).
        if (i1 < N) compute_f(i1, s1, fC);
        else {
#pragma unroll
            for (int j = 0; j < 8; j++) fC[j] = 0.f;
        }
        if (i2 < N) compute_f(i2, s2, fD);
        else {
#pragma unroll
            for (int j = 0; j < 8; j++) fD[j] = 0.f;
        }

        // Joint LN2: both rows' partial sums reduced in ONE 4-chain tree.
        float h0[8], h1[8], sm0, sq0, sm1, sq1;
        conv_h(i,  fA, fB, fC, i  > sb,  i1 < se,  h0, sm0, sq0);
        conv_h(i1, fB, fC, fD, i1 > sb1, i2 < se1, h1, sm1, sq1);
        warp_red4(sm0, sq0, sm1, sq1);
        store_ln(i,  h0, sm0, sq0);
        store_ln(i1, h1, sm1, sq1);

#pragma unroll
        for (int j = 0; j < 8; j++) { fA[j] = fC[j]; fB[j] = fD[j]; }
        s = s2; sb = sb2; se = se2;
    }
}

// ---------------------------------------------------------------------------
extern "C" void kernel_launch(void* const* d_in, const int* in_sizes, int n_in,
                              void* d_out, int out_size) {
    const float* feat   = (const float*)d_in[0];
    const float* coord  = (const float*)d_in[1];
    const void*  lens   = d_in[2];
    const float* w_xyz  = (const float*)d_in[3];
    const float* b_xyz  = (const float*)d_in[4];
    const float* g1     = (const float*)d_in[5];
    const float* be1    = (const float*)d_in[6];
    const float* w_conv = (const float*)d_in[7];
    const float* b_conv = (const float*)d_in[8];
    const float* g2     = (const float*)d_in[9];
    const float* be2    = (const float*)d_in[10];

    int N = in_sizes[0] / C_DIM;
    int B = in_sizes[2];
    if (B > MAX_B) B = MAX_B;

    prep_kernel<<<B + 1, 1024>>>(coord, lens, w_xyz, b_xyz, N, B);

    int warps  = (N + ROWS - 1) / ROWS;
    int blocks = (warps + 7) / 8;
    fused_xcpe_kernel<<<blocks, 256>>>(feat, coord, w_xyz, b_xyz, g1, be1,
                                       w_conv, b_conv, g2, be2,
                                       (float*)d_out, N);
}

// round 15
// speedup vs baseline: 1.4308x; 1.4308x over previous
#include <cuda_runtime.h>
#include <math.h>

#define C_DIM 256
#define ROWS  16          // rows (points) per warp (even; pairing step = 2)
#define MAX_B 1024

__device__ int   d_off[MAX_B + 1];
__device__ float d_mean[MAX_B * 3];
// Quadratic-form coefficients for analytic LN1 stats.
__device__ float d_qc[14];

__device__ __forceinline__ void warp_red4(float& a, float& b, float& c, float& d) {
#pragma unroll
    for (int o = 16; o; o >>= 1) {
        a += __shfl_xor_sync(0xffffffffu, a, o);
        b += __shfl_xor_sync(0xffffffffu, b, o);
        c += __shfl_xor_sync(0xffffffffu, c, o);
        d += __shfl_xor_sync(0xffffffffu, d, o);
    }
}

// HW tanh (sm_75+ MUFU): ~16cyc, replaces the ~15-instr erff polynomial.
__device__ __forceinline__ float tanh_hw(float x) {
    float r;
    asm("tanh.approx.f32 %0, %1;" : "=f"(r) : "f"(x));
    return r;
}

// GELU, tanh form (|err vs exact-erf GELU| ~3e-4 abs incl. MUFU error).
__device__ __forceinline__ float gelu_fast(float t) {
    float t2 = t * t;
    float inner = 0.7978845608028654f * fmaf(0.044715f * t2, t, t);
    return 0.5f * t * (1.0f + tanh_hw(inner));
}

// ---------------------------------------------------------------------------
// Prep kernel: blocks 0..B-1 per-scene coord means + offsets; block B the 14
// quadratic-form coefficients.
// ---------------------------------------------------------------------------
__global__ void prep_kernel(const float* __restrict__ coord,
                            const void* __restrict__ lengths_raw,
                            const float* __restrict__ w_xyz,
                            const float* __restrict__ b_xyz,
                            int N, int B) {
    if ((int)blockIdx.x == B) {
        if (threadIdx.x < 256) {
            int c = threadIdx.x;
            float w0 = w_xyz[c];
            float w1 = w_xyz[C_DIM + c];
            float w2 = w_xyz[2 * C_DIM + c];
            float bb = b_xyz[c];
            float loc[14] = { w0, w1, w2, bb,
                              w0 * w0, w1 * w1, w2 * w2,
                              w0 * w1, w0 * w2, w1 * w2,
                              w0 * bb, w1 * bb, w2 * bb,
                              bb * bb };
#pragma unroll
            for (int k = 0; k < 14; k++)
#pragma unroll
                for (int o = 16; o; o >>= 1)
                    loc[k] += __shfl_xor_sync(0xffffffffu, loc[k], o);
            __shared__ float sh[8][14];
            int w = threadIdx.x >> 5, l = threadIdx.x & 31;
            if (l == 0)
#pragma unroll
                for (int k = 0; k < 14; k++) sh[w][k] = loc[k];
            __syncthreads();
            if (threadIdx.x == 0) {
#pragma unroll
                for (int k = 0; k < 14; k++) {
                    double s = 0.0;
                    for (int ww = 0; ww < 8; ww++) s += (double)sh[ww][k];
                    d_qc[k] = (float)s;
                }
            }
        }
        return;
    }

    int b = blockIdx.x;
    __shared__ long long sh_start, sh_len;
    if (threadIdx.x == 0) {
        const int* i32 = (const int*)lengths_raw;
        long long sum32 = 0;
        for (int k = 0; k < B; k++) sum32 += (long long)i32[k];
        bool is64 = (sum32 != (long long)N);
        const long long* i64 = (const long long*)lengths_raw;
        long long start = 0;
        for (int k = 0; k < b; k++)
            start += is64 ? i64[k] : (long long)i32[k];
        long long len = is64 ? i64[b] : (long long)i32[b];
        sh_start = start;
        sh_len   = len;
        d_off[b] = (int)start;
        if (b == B - 1) d_off[B] = (int)(start + len);
    }
    __syncthreads();
    long long start = sh_start, len = sh_len;

    float sx = 0.f, sy = 0.f, sz = 0.f;
    for (long long t = threadIdx.x; t < len; t += blockDim.x) {
        const float* p = coord + (start + t) * 3;
        sx += p[0]; sy += p[1]; sz += p[2];
    }
#pragma unroll
    for (int o = 16; o; o >>= 1) {
        sx += __shfl_xor_sync(0xffffffffu, sx, o);
        sy += __shfl_xor_sync(0xffffffffu, sy, o);
        sz += __shfl_xor_sync(0xffffffffu, sz, o);
    }
    __shared__ float red[32][3];
    int w = threadIdx.x >> 5, l = threadIdx.x & 31;
    if (l == 0) { red[w][0] = sx; red[w][1] = sy; red[w][2] = sz; }
    __syncthreads();
    if (threadIdx.x == 0) {
        float ax = 0.f, ay = 0.f, az = 0.f;
        int nw = (blockDim.x + 31) >> 5;
        for (int k = 0; k < nw; k++) { ax += red[k][0]; ay += red[k][1]; az += red[k][2]; }
        long long d = len > 0 ? len : 1;
        float inv = 1.0f / (float)d;
        d_mean[b * 3 + 0] = ax * inv;
        d_mean[b * 3 + 1] = ay * inv;
        d_mean[b * 3 + 2] = az * inv;
    }
}

// ---------------------------------------------------------------------------
// Fused kernel (R11 structure: 128 regs, 2 blocks/SM, conv params in regs).
// Transposed conflict-free WIDE param layout:
//   s_wb[j*32+lane]  = float4{w0,w1,w2,bx}  (LDS.128)
//   s_ab1[j*32+lane] = float2{g1,be1}        (LDS.64)
//   s_ab2[j*32+lane] = float2{g2,be2}        (LDS.64)
// GELU via HW tanh.approx. Joint 4-chain LN2 reduction per row pair.
// ---------------------------------------------------------------------------
__global__ void __launch_bounds__(256, 2)
fused_xcpe_kernel(const float* __restrict__ feat,
                  const float* __restrict__ coord,
                  const float* __restrict__ w_xyz,  const float* __restrict__ b_xyz,
                  const float* __restrict__ g1,     const float* __restrict__ be1,
                  const float* __restrict__ w_conv, const float* __restrict__ b_conv,
                  const float* __restrict__ g2,     const float* __restrict__ be2,
                  float* __restrict__ out, int N) {
    __shared__ float4 s_wb[C_DIM];            // 4 KB
    __shared__ float2 s_ab1[C_DIM];           // 2 KB
    __shared__ float2 s_ab2[C_DIM];           // 2 KB
    __shared__ float  sqc[14];
    for (int idx = threadIdx.x; idx < C_DIM; idx += blockDim.x) {
        int l = idx & 31, j = idx >> 5;
        int c = l * 8 + j;
        s_wb[idx]  = make_float4(w_xyz[c], w_xyz[C_DIM + c], w_xyz[2 * C_DIM + c], b_xyz[c]);
        s_ab1[idx] = make_float2(g1[c], be1[c]);
        s_ab2[idx] = make_float2(g2[c], be2[c]);
    }
    if (threadIdx.x < 14) sqc[threadIdx.x] = d_qc[threadIdx.x];
    __syncthreads();

    const int lane = threadIdx.x & 31;
    const int warp = blockIdx.x * (blockDim.x >> 5) + (threadIdx.x >> 5);
    int r0 = warp * ROWS;
    if (r0 >= N) return;
    int r1 = min(r0 + ROWS, N);
    const int c0 = lane * 8;

    // Conv params in registers (zero-issue access). (NOT smem — R12 spilled.)
    float bcv[8], wc0[8], wc1[8], wc2[8];
    {
        float4 t0 = *(const float4*)(b_conv + c0);
        float4 t1 = *(const float4*)(b_conv + c0 + 4);
        bcv[0]=t0.x; bcv[1]=t0.y; bcv[2]=t0.z; bcv[3]=t0.w;
        bcv[4]=t1.x; bcv[5]=t1.y; bcv[6]=t1.z; bcv[7]=t1.w;
    }
#pragma unroll
    for (int j = 0; j < 8; j++) {
        wc0[j] = w_conv[(c0 + j) * 3 + 0];
        wc1[j] = w_conv[(c0 + j) * 3 + 1];
        wc2[j] = w_conv[(c0 + j) * 3 + 2];
    }

    int s = 0;
    while (r0 >= d_off[s + 1]) s++;
    int sb = d_off[s], se = d_off[s + 1];

    float fA[8], fB[8], fC[8], fD[8];

    // f(i) = feat(i) + gelu(LN1(xyz_c @ W + b)), analytic LN1 stats.
    auto compute_f = [&](int i, int sc, float* f) {
        const float* frow = feat + (size_t)i * C_DIM + c0;
        float4 e0 = *(const float4*)frow;
        float4 e1 = *(const float4*)(frow + 4);
        float x = coord[3 * i + 0] - d_mean[sc * 3 + 0];
        float y = coord[3 * i + 1] - d_mean[sc * 3 + 1];
        float z = coord[3 * i + 2] - d_mean[sc * 3 + 2];
        float mu = fmaf(x, sqc[0], fmaf(y, sqc[1], fmaf(z, sqc[2], sqc[3]))) * (1.0f / C_DIM);
        float q  = fmaf(x * x, sqc[4],
                   fmaf(y * y, sqc[5],
                   fmaf(z * z, sqc[6], sqc[13])));
        float qx = fmaf(x * y, sqc[7],
                   fmaf(x * z, sqc[8],
                   fmaf(y * z, sqc[9],
                   fmaf(x, sqc[10], fmaf(y, sqc[11], z * sqc[12])))));
        float var = fmaf(2.0f, qx, q) * (1.0f / C_DIM) - mu * mu;
        float rs  = rsqrtf(var + 1e-5f);
        float fe[8] = { e0.x, e0.y, e0.z, e0.w, e1.x, e1.y, e1.z, e1.w };
#pragma unroll
        for (int j = 0; j < 8; j++) {
            float4 wb = s_wb[j * 32 + lane];
            float2 ab = s_ab1[j * 32 + lane];
            float v = fmaf(x, wb.x, fmaf(y, wb.y, fmaf(z, wb.z, wb.w)));
            float t  = fmaf((v - mu) * rs, ab.x, ab.y);
            f[j] = fe[j] + gelu_fast(t);
        }
    };

    // Conv + residual for one row; accumulates LN2 partial sums.
    auto conv_h = [&](int i, const float* fp, const float* fc, const float* fn,
                      bool hasP, bool hasN, float* h, float& sm, float& sq) {
        const float* frow = feat + (size_t)i * C_DIM + c0;
        float4 e0 = *(const float4*)frow;
        float4 e1 = *(const float4*)(frow + 4);
        float fe[8] = { e0.x, e0.y, e0.z, e0.w, e1.x, e1.y, e1.z, e1.w };
        sm = 0.f; sq = 0.f;
        if (hasP & hasN) {
#pragma unroll
            for (int j = 0; j < 8; j++) {
                float cv = fmaf(wc0[j], fp[j],
                           fmaf(wc1[j], fc[j],
                           fmaf(wc2[j], fn[j], bcv[j])));
                float hh = fe[j] + cv;
                h[j] = hh; sm += hh; sq = fmaf(hh, hh, sq);
            }
        } else {
            float mp = hasP ? 1.f : 0.f, mn = hasN ? 1.f : 0.f;
#pragma unroll
            for (int j = 0; j < 8; j++) {
                float cv = fmaf(wc0[j], mp * fp[j],
                           fmaf(wc1[j], fc[j],
                           fmaf(wc2[j], mn * fn[j], bcv[j])));
                float hh = fe[j] + cv;
                h[j] = hh; sm += hh; sq = fmaf(hh, hh, sq);
            }
        }
    };

    // LN2 affine + store for one row given reduced stats.
    auto store_ln = [&](int i, const float* h, float sm, float sq) {
        float mu  = sm * (1.0f / C_DIM);
        float var = sq * (1.0f / C_DIM) - mu * mu;
        float rs  = rsqrtf(var + 1e-5f);
        float o[8];
#pragma unroll
        for (int j = 0; j < 8; j++) {
            float2 ab = s_ab2[j * 32 + lane];
            o[j] = fmaf((h[j] - mu) * rs, ab.x, ab.y);
        }
        float* orow = out + (size_t)i * C_DIM + c0;
        *(float4*)orow       = make_float4(o[0], o[1], o[2], o[3]);
        *(float4*)(orow + 4) = make_float4(o[4], o[5], o[6], o[7]);
    };

    // Prologue.
    if (r0 > 0) compute_f(r0 - 1, s, fA);
    else {
#pragma unroll
        for (int j = 0; j < 8; j++) fA[j] = 0.f;
    }
    compute_f(r0, s, fB);

    for (int i = r0; i < r1; i += 2) {
        int i1 = i + 1, i2 = i + 2;
        int s1 = s, sb1 = sb, se1 = se;
        if (i1 < N) { while (i1 >= se1) { s1++; sb1 = se1; se1 = d_off[s1 + 1]; } }
        int s2 = s1, sb2 = sb1, se2 = se1;
        if (i2 < N) { while (i2 >= se2) { s2++; sb2 = se2; se2 = d_off[s2 + 1]; } }

        // Two independent compute_f chains (ILP on MUFU + LDG).
        if (i1 < N) compute_f(i1, s1, fC);
        else {
#pragma unroll
            for (int j = 0; j < 8; j++) fC[j] = 0.f;
        }
        if (i2 < N) compute_f(i2, s2, fD);
        else {
#pragma unroll
            for (int j = 0; j < 8; j++) fD[j] = 0.f;
        }

        // Joint LN2: both rows' partial sums reduced in ONE 4-chain tree.
        float h0[8], h1[8], sm0, sq0, sm1, sq1;
        conv_h(i,  fA, fB, fC, i  > sb,  i1 < se,  h0, sm0, sq0);
        conv_h(i1, fB, fC, fD, i1 > sb1, i2 < se1, h1, sm1, sq1);
        warp_red4(sm0, sq0, sm1, sq1);
        store_ln(i,  h0, sm0, sq0);
        store_ln(i1, h1, sm1, sq1);

#pragma unroll
        for (int j = 0; j < 8; j++) { fA[j] = fC[j]; fB[j] = fD[j]; }
        s = s2; sb = sb2; se = se2;
    }
}

// ---------------------------------------------------------------------------
extern "C" void kernel_launch(void* const* d_in, const int* in_sizes, int n_in,
                              void* d_out, int out_size) {
    const float* feat   = (const float*)d_in[0];
    const float* coord  = (const float*)d_in[1];
    const void*  lens   = d_in[2];
    const float* w_xyz  = (const float*)d_in[3];
    const float* b_xyz  = (const float*)d_in[4];
    const float* g1     = (const float*)d_in[5];
    const float* be1    = (const float*)d_in[6];
    const float* w_conv = (const float*)d_in[7];
    const float* b_conv = (const float*)d_in[8];
    const float* g2     = (const float*)d_in[9];
    const float* be2    = (const float*)d_in[10];

    int N = in_sizes[0] / C_DIM;
    int B = in_sizes[2];
    if (B > MAX_B) B = MAX_B;

    prep_kernel<<<B + 1, 1024>>>(coord, lens, w_xyz, b_xyz, N, B);

    int warps  = (N + ROWS - 1) / ROWS;
    int blocks = (warps + 7) / 8;
    fused_xcpe_kernel<<<blocks, 256>>>(feat, coord, w_xyz, b_xyz, g1, be1,
                                       w_conv, b_conv, g2, be2,
                                       (float*)d_out, N);
}